// round 12
// baseline (speedup 1.0000x reference)
#include <cuda_runtime.h>
#include <math.h>

#ifndef M_PI
#define M_PI 3.14159265358979323846
#endif

#define ANGN 9
#define NUV 81
#define CH 3
#define HH 128
#define NF 16
#define NBLK 2
#define HW (HH*HH)            // 16384
#define S_UVHW (NUV*HW)       // 1327104

#define NTILE 1296            // 81 planes * 8 bh * 2 bw
#define NITEM (3*NTILE)
#define CGRID 296             // 2 * 148 (all-resident on 148- or 152-SM parts)

typedef unsigned long long ull;

__device__ __forceinline__ ull pack2(float lo, float hi) {
    ull r; asm("mov.b64 %0,{%1,%2};" : "=l"(r) : "f"(lo), "f"(hi)); return r;
}
__device__ __forceinline__ void unpack2(ull v, float& lo, float& hi) {
    asm("mov.b64 {%0,%1},%2;" : "=f"(lo), "=f"(hi) : "l"(v));
}
__device__ __forceinline__ void fma2(ull& d, ull a, ull b) {
    asm("fma.rn.f32x2 %0,%1,%2,%0;" : "+l"(d) : "l"(a), "l"(b));
}

// ---------------- device global scratch ----------------
__device__ float g_Ds[HH*HH];
__device__ float g_DsT[HH*HH];
__device__ float g_Da[81];
__device__ float g_DaT[81];

__device__ float g_b1[CH*S_UVHW];
__device__ float g_b2[CH*S_UVHW];
__device__ float g_y0[NF*S_UVHW];
__device__ float g_y1[NF*S_UVHW];
__device__ float g_p0[NF*S_UVHW];   // prelu(y0, a0)
__device__ float g_p1[NF*S_UVHW];   // prelu(y1, a1)

// transposed weights: [set][(ic*27+t)*NF + o]
__device__ float g_wti[4*CH*27*NF];        // init conv (4 branches)
__device__ float g_wtb[4*NBLK*NF*27*NF];   // resblocks (8 sets)
__device__ float g_bi[4*NF];
__device__ float g_bb[4*NBLK*NF];
__device__ float g_al[4*NBLK];             // prelu alphas

__device__ int g_flags[2*NTILE];           // tile-completion flags, layers 0/1

// ---------------- DCT matrix init (exact integer range reduction + cosf) ----
__global__ void init_mats_kernel() {
    int tid = blockIdx.x*blockDim.x + threadIdx.x;
    int stride = gridDim.x*blockDim.x;
    const float sc_s = sqrtf(2.0f/HH);
    const float st_s = (float)(M_PI/256.0);   // pi/(2*128)
    for (int idx = tid; idx < HH*HH; idx += stride) {
        int k = idx / HH, i = idx % HH;
        int m = ((2*i+1)*k) & 511;             // mod 4n, n=128
        float f = cosf((float)m * st_s) * sc_s;
        if (k==0) f *= 0.70710678f;
        g_Ds[k*HH+i] = f;
        g_DsT[i*HH+k] = f;
    }
    const float sc_a = sqrtf(2.0f/9.0f);
    const float st_a = (float)(M_PI/18.0);
    for (int idx = tid; idx < 81; idx += stride) {
        int k = idx/9, i = idx%9;
        int m = ((2*i+1)*k) % 36;
        float f = cosf((float)m * st_a) * sc_a;
        if (k==0) f *= 0.70710678f;
        g_Da[k*9+i] = f;
        g_DaT[i*9+k] = f;
    }
}

// ---------------- weight packing (transpose to [ict][o]) + flag reset -------
struct PackPtrs {
    const float* wi[4];
    const float* bi[4];
    const float* al[4];
    const float* wb[4];
    const float* bb[4];
};

__global__ void pack_kernel(PackPtrs pp) {
    int g = blockIdx.x*blockDim.x + threadIdx.x;
    int stride = gridDim.x*blockDim.x;
    for (int i = g; i < 4*CH*27*NF; i += stride) {
        int widx = i / (CH*27*NF);
        int r = i - widx*(CH*27*NF);
        int ict = r >> 4, o = r & 15;
        g_wti[i] = pp.wi[widx][o*(CH*27) + ict];
    }
    for (int i = g; i < 4*NBLK*NF*27*NF; i += stride) {
        int sel = i / (NF*27*NF);
        int r = i - sel*(NF*27*NF);
        int ict = r >> 4, o = r & 15;
        int branch = sel >> 1, k = sel & 1;
        g_wtb[i] = pp.wb[branch][k*(NF*NF*27) + o*(NF*27) + ict];
    }
    for (int i = g; i < 4*NF; i += stride)       g_bi[i] = pp.bi[i/NF][i%NF];
    for (int i = g; i < 4*NBLK; i += stride)     g_al[i] = pp.al[i/NBLK][i%NBLK];
    for (int i = g; i < 4*NBLK*NF; i += stride)  g_bb[i] = pp.bb[i/(NBLK*NF)][i%(NBLK*NF)];
    for (int i = g; i < 2*NTILE; i += stride)    g_flags[i] = 0;
}

// ---------------- spatial DCT: Y = M X M^T per 128x128 image ----------------
#define DPAD 129
#define DCT_SMEM ((2*HH + 64)*DPAD*4)

__global__ void dct_spatial_kernel(const float* __restrict__ x, float* __restrict__ dout, int mode) {
    extern __shared__ float sm[];
    float* Ms = sm;
    float* Xs = sm + HH*DPAD;
    float* Ts = sm + 2*HH*DPAD;     // 64 rows
    int bid = blockIdx.x;           // 0..485
    int half = bid & 1;
    int uvc = bid >> 1;
    int uv = uvc / CH, c = uvc % CH;
    int r0 = half*64;
    int tid = threadIdx.x;

    const float* Msrc = mode ? g_DsT : g_Ds;
    const float* src  = mode ? (g_b2 + (c*NUV+uv)*HW) : (x + (uv*CH+c)*HW);

    for (int l = tid; l < HH*HH; l += 256) {
        int r = l >> 7, cc = l & 127;
        Ms[r*DPAD + cc] = Msrc[l];
        Xs[r*DPAD + cc] = src[l];
    }
    __syncthreads();

    int tx = tid & 15, ty = tid >> 4;
    ull acc[4][4];
    #pragma unroll
    for (int i=0;i<4;i++)
        #pragma unroll
        for (int jp=0;jp<4;jp++) acc[i][jp] = 0ull;

    for (int kk = 0; kk < HH; kk++) {
        ull ad[4], bp[4];
        #pragma unroll
        for (int i=0;i<4;i++) {
            float a = Ms[(r0+ty+16*i)*DPAD + kk];
            ad[i] = pack2(a, a);
        }
        #pragma unroll
        for (int jp=0;jp<4;jp++)
            bp[jp] = pack2(Xs[kk*DPAD + tx + 32*jp], Xs[kk*DPAD + tx + 32*jp + 16]);
        #pragma unroll
        for (int i=0;i<4;i++)
            #pragma unroll
            for (int jp=0;jp<4;jp++) fma2(acc[i][jp], ad[i], bp[jp]);
    }
    #pragma unroll
    for (int i=0;i<4;i++)
        #pragma unroll
        for (int jp=0;jp<4;jp++) {
            float lo, hi; unpack2(acc[i][jp], lo, hi);
            Ts[(ty+16*i)*DPAD + tx + 32*jp]      = lo;
            Ts[(ty+16*i)*DPAD + tx + 32*jp + 16] = hi;
        }
    __syncthreads();

    #pragma unroll
    for (int i=0;i<4;i++)
        #pragma unroll
        for (int jp=0;jp<4;jp++) acc[i][jp] = 0ull;

    for (int kk = 0; kk < HH; kk++) {
        ull ad[4], bp[4];
        #pragma unroll
        for (int i=0;i<4;i++) {
            float a = Ts[(ty+16*i)*DPAD + kk];
            ad[i] = pack2(a, a);
        }
        #pragma unroll
        for (int jp=0;jp<4;jp++)
            bp[jp] = pack2(Ms[(tx+32*jp)*DPAD + kk], Ms[(tx+32*jp+16)*DPAD + kk]);
        #pragma unroll
        for (int i=0;i<4;i++)
            #pragma unroll
            for (int jp=0;jp<4;jp++) fma2(acc[i][jp], ad[i], bp[jp]);
    }

    if (mode == 0) {
        float* dst = g_b1 + (c*NUV+uv)*HW;
        #pragma unroll
        for (int i=0;i<4;i++)
            #pragma unroll
            for (int jp=0;jp<4;jp++) {
                float lo, hi; unpack2(acc[i][jp], lo, hi);
                dst[(r0+ty+16*i)*HH + tx+32*jp]      = lo;
                dst[(r0+ty+16*i)*HH + tx+32*jp + 16] = hi;
            }
    } else {
        const float* xa = x + (uv*CH+c)*HW;
        float* dst = dout + (uv*CH+c)*HW;
        #pragma unroll
        for (int i=0;i<4;i++)
            #pragma unroll
            for (int jp=0;jp<4;jp++) {
                float lo, hi; unpack2(acc[i][jp], lo, hi);
                int o0 = (r0+ty+16*i)*HH + tx+32*jp;
                int o1 = o0 + 16;
                dst[o0] = lo + xa[o0];
                dst[o1] = hi + xa[o1];
            }
    }
}

// ---------------- angular DCT ----------------
__global__ void dct_ang_kernel(int mode) {
    __shared__ float M[81];
    int tid = threadIdx.x;
    if (tid < 81) M[tid] = mode ? g_DaT[tid] : g_Da[tid];
    __syncthreads();
    int g = blockIdx.x*blockDim.x + tid;     // 0..49151
    if (g >= CH*HW) return;
    int c = g / HW, p = g % HW;

    const float* in = g_b1 + c*S_UVHW + p;
    float T[81];
    #pragma unroll
    for (int i=0;i<81;i++) T[i] = 0.f;

    #pragma unroll
    for (int u=0;u<9;u++) {
        #pragma unroll
        for (int v=0;v<9;v++) {
            float xv = in[(u*9+v)*HW];
            #pragma unroll
            for (int U=0;U<9;U++) T[U*9+v] += M[U*9+u]*xv;
        }
    }
    float* outp = g_b2 + c*S_UVHW + p;
    #pragma unroll
    for (int U=0;U<9;U++) {
        #pragma unroll
        for (int V=0;V<9;V++) {
            float o = 0.f;
            #pragma unroll
            for (int v=0;v<9;v++) o += T[U*9+v]*M[V*9+v];
            outp[(U*9+V)*HW] = o;
        }
    }
}

// ---------------- 3x3x3 conv tile body (f32x2 oc-paired) ----------------
#define TPL (18*66)          // 1188
#define TPL3 (3*TPL)         // 3564
#define CONV_SMEM ((NF*NF*27 + NF + 48 + 2*TPL3)*4)

template<int CIN, bool RES, bool WRITE_P, bool MIX>
__device__ __forceinline__ void conv3d_body(
    int uv, int bh, int bw,
    const float* __restrict__ in, const float* __restrict__ res,
    float* __restrict__ out, float* __restrict__ pout, float palpha,
    const float* __restrict__ Wt, const float* __restrict__ Bsel,
    const float* __restrict__ wl, const float* __restrict__ mix_extra,
    float* __restrict__ mix_out)
{
    extern __shared__ float sm[];
    float* sw = sm;                         // CIN*27*NF floats, [ict][o]
    float* sb = sw + CIN*27*NF;
    float* sl = sb + NF;                    // 48 mix weights
    float* st = sl + 48;                    // even word offset -> 8B aligned
    const ull* swp = (const ull*)sw;

    const int tid = threadIdx.x;
    const int tx = tid & 15, ty = tid >> 4;
    const int u = uv/9, v = uv - 9*u;
    const int h0 = bh*16, w0 = bw*64;
    const int nb0 = (u > 0 && v < 8) ? uv-8 : -1;   // (u-1,v+1)
    const int nb2 = (u < 8 && v > 0) ? uv+8 : -1;   // (u+1,v-1)

    for (int l = tid; l < CIN*27*NF; l += 256) sw[l] = Wt[l];
    if (tid < NF) sb[tid] = Bsel[tid];
    if (MIX && tid < CH*NF) sl[tid] = wl[tid];

    int offs[14]; unsigned vmask = 0;
    #pragma unroll
    for (int j = 0; j < 14; j++) {
        int l = tid + j*256;
        offs[j] = 0;
        if (l < TPL3) {
            int d = l / TPL;
            int rem = l - d*TPL;
            int r = rem / 66;
            int cc = rem - r*66;
            int gh = h0 - 1 + r, gw = w0 - 1 + cc;
            int uvd = (d==0) ? nb0 : ((d==1) ? uv : nb2);
            if (uvd >= 0 && (unsigned)gh < (unsigned)HH && (unsigned)gw < (unsigned)HH) {
                vmask |= 1u << j;
                offs[j] = (uvd << 14) + (gh << 7) + gw;
            }
        }
    }

    auto fill = [&](const float* icin, float* nbuf) {
        unsigned sbase = (unsigned)__cvta_generic_to_shared(nbuf);
        #pragma unroll
        for (int j = 0; j < 14; j++) {
            int l = tid + j*256;
            if (l < TPL3) {
                unsigned sa = sbase + (unsigned)l*4u;
                const float* ga = icin + offs[j];
                int sz = ((vmask >> j) & 1u) ? 4 : 0;
                asm volatile("cp.async.ca.shared.global [%0], [%1], 4, %2;"
                             :: "r"(sa), "l"(ga), "r"(sz));
            }
        }
        asm volatile("cp.async.commit_group;");
    };

    fill(in, st);
    asm volatile("cp.async.wait_group 0;");
    __syncthreads();

    ull acc[8][4];
    #pragma unroll
    for (int op=0;op<8;op++)
        #pragma unroll
        for (int p=0;p<4;p++) acc[op][p] = 0ull;

    #pragma unroll 1
    for (int ic = 0; ic < CIN; ic++) {
        if (ic + 1 < CIN) fill(in + (ic+1)*(NUV*HW), st + ((ic+1) & 1)*TPL3);

        const float* base = st + (ic & 1)*TPL3;
        #pragma unroll 1
        for (int d = 0; d < 3; d++) {
            if (d == 0 && nb0 < 0) continue;
            if (d == 2 && nb2 < 0) continue;
            #pragma unroll 1
            for (int dh = 0; dh < 3; dh++) {
                const ull* row = (const ull*)(base + d*TPL + (ty+dh)*66 + tx*4);
                ull p01 = row[0], p23 = row[1], p45 = row[2];
                float i0,i1,i2,i3,i4,i5;
                unpack2(p01, i0, i1); unpack2(p23, i2, i3); unpack2(p45, i4, i5);
                ull dd0 = pack2(i0,i0), dd1 = pack2(i1,i1), dd2 = pack2(i2,i2);
                ull dd3 = pack2(i3,i3), dd4 = pack2(i4,i4), dd5 = pack2(i5,i5);
                ull dv[6] = {dd0, dd1, dd2, dd3, dd4, dd5};
                const ulonglong2* wt2 = (const ulonglong2*)(swp + (ic*27 + d*9 + dh*3)*(NF/2));
                #pragma unroll
                for (int dw = 0; dw < 3; dw++) {
                    #pragma unroll
                    for (int q = 0; q < 4; q++) {
                        ulonglong2 wp = wt2[dw*4 + q];
                        int op = 2*q;
                        fma2(acc[op][0], dv[dw+0], wp.x);
                        fma2(acc[op][1], dv[dw+1], wp.x);
                        fma2(acc[op][2], dv[dw+2], wp.x);
                        fma2(acc[op][3], dv[dw+3], wp.x);
                        fma2(acc[op+1][0], dv[dw+0], wp.y);
                        fma2(acc[op+1][1], dv[dw+1], wp.y);
                        fma2(acc[op+1][2], dv[dw+2], wp.y);
                        fma2(acc[op+1][3], dv[dw+3], wp.y);
                    }
                }
            }
        }
        if (ic + 1 < CIN) {
            asm volatile("cp.async.wait_group 0;");
            __syncthreads();
        }
    }

    const int gh = h0 + ty;
    const int pbase = (gh << 7) + w0 + tx*4;
    float4 macc[3];
    if (MIX) { macc[0] = make_float4(0,0,0,0); macc[1] = macc[0]; macc[2] = macc[0]; }

    #pragma unroll
    for (int op = 0; op < 8; op++) {
        float e0[4], e1[4];
        #pragma unroll
        for (int p = 0; p < 4; p++) unpack2(acc[op][p], e0[p], e1[p]);
        #pragma unroll
        for (int half = 0; half < 2; half++) {
            int o = 2*op + half;
            const float* ev = half ? e1 : e0;
            float bias = sb[o];
            int obase = ((o*NUV+uv) << 14) + pbase;
            float4 r4;
            r4.x = ev[0] + bias; r4.y = ev[1] + bias;
            r4.z = ev[2] + bias; r4.w = ev[3] + bias;
            if (RES) {
                float4 rr = *(const float4*)&res[obase];
                r4.x += rr.x; r4.y += rr.y; r4.z += rr.z; r4.w += rr.w;
            }
            if (MIX) {
                float4 y0v = *(const float4*)&mix_extra[obase];
                float tx0 = r4.x + y0v.x, tx1 = r4.y + y0v.y;
                float tx2 = r4.z + y0v.z, tx3 = r4.w + y0v.w;
                #pragma unroll
                for (int cc = 0; cc < 3; cc++) {
                    float wv = sl[cc*NF + o];
                    macc[cc].x += wv*tx0; macc[cc].y += wv*tx1;
                    macc[cc].z += wv*tx2; macc[cc].w += wv*tx3;
                }
            } else {
                *(float4*)&out[obase] = r4;
                if (WRITE_P) {
                    float4 p4;
                    p4.x = (r4.x >= 0.f) ? r4.x : palpha*r4.x;
                    p4.y = (r4.y >= 0.f) ? r4.y : palpha*r4.y;
                    p4.z = (r4.z >= 0.f) ? r4.z : palpha*r4.z;
                    p4.w = (r4.w >= 0.f) ? r4.w : palpha*r4.w;
                    *(float4*)&pout[obase] = p4;
                }
            }
        }
    }
    if (MIX) {
        #pragma unroll
        for (int cc = 0; cc < 3; cc++)
            *(float4*)&mix_out[((cc*NUV+uv) << 14) + pbase] = macc[cc];
    }
}

__device__ __forceinline__ int branch_idx(int uv) {
    int u = uv/9, s = u + (uv - 9*u);
    return (s==0) ? 0 : (s<=2 ? 1 : (s<=8 ? 2 : 3));
}

// ---------------- persistent fused conv: 3 layers, flag-pipelined -----------
__global__ void __launch_bounds__(256,2) conv_fused_kernel(const float* __restrict__ wl) {
    __shared__ int s_deps[27];
    __shared__ int s_nd;
    const int tid = threadIdx.x;

    for (int item = blockIdx.x; item < NITEM; item += CGRID) {
        int L = item / NTILE;
        int t = item - L*NTILE;
        int uv = t >> 4;
        int r = t & 15;
        int bh = r >> 1, bw = r & 1;

        // ---- wait on producer tiles (layer L-1, 3x3x3 tile neighborhood) ----
        if (tid == 0) {
            int nd = 0;
            if (L > 0) {
                int u = uv/9, v = uv - 9*u;
                int uvl[3]; int nu = 0;
                if (u > 0 && v < 8) uvl[nu++] = uv - 8;
                uvl[nu++] = uv;
                if (u < 8 && v > 0) uvl[nu++] = uv + 8;
                int bhl = (bh > 0) ? bh-1 : 0, bhr = (bh < 7) ? bh+1 : 7;
                int bwl = (bw > 0) ? bw-1 : 0, bwr = (bw < 1) ? bw+1 : 1;
                for (int a = 0; a < nu; a++)
                    for (int b2 = bhl; b2 <= bhr; b2++)
                        for (int w2 = bwl; w2 <= bwr; w2++)
                            s_deps[nd++] = (L-1)*NTILE + uvl[a]*16 + b2*2 + w2;
            }
            s_nd = nd;
        }
        __syncthreads();
        if (tid < s_nd) {
            int* f = &g_flags[s_deps[tid]];
            int vv;
            while (true) {
                asm volatile("ld.acquire.gpu.b32 %0,[%1];" : "=r"(vv) : "l"(f));
                if (vv) break;
                __nanosleep(64);
            }
        }
        __syncthreads();

        // ---- run the tile ----
        int widx = branch_idx(uv);
        if (L == 0) {
            float pa = g_al[widx*NBLK + 0];
            conv3d_body<CH,false,true,false>(uv, bh, bw, g_b2, nullptr, g_y0, g_p0, pa,
                g_wti + widx*(CH*27*NF), g_bi + widx*NF, nullptr, nullptr, nullptr);
        } else if (L == 1) {
            float pa = g_al[widx*NBLK + 1];
            int sel = widx*NBLK + 0;
            conv3d_body<NF,true,true,false>(uv, bh, bw, g_p0, g_y0, g_y1, g_p1, pa,
                g_wtb + sel*(NF*27*NF), g_bb + sel*NF, nullptr, nullptr, nullptr);
        } else {
            int sel = widx*NBLK + 1;
            conv3d_body<NF,true,false,true>(uv, bh, bw, g_p1, g_y1, nullptr, nullptr, 0.f,
                g_wtb + sel*(NF*27*NF), g_bb + sel*NF, wl, g_y0, g_b1);
        }

        // ---- publish ----
        if (L < 2) {
            __threadfence();
            __syncthreads();
            if (tid == 0)
                asm volatile("st.release.gpu.b32 [%0],%1;" :: "l"(&g_flags[item]), "r"(1) : "memory");
        } else {
            __syncthreads();   // keep smem reuse safe across items
        }
    }
}

// ---------------- launch ----------------
extern "C" void kernel_launch(void* const* d_in, const int* in_sizes, int n_in,
                              void* d_out, int out_size) {
    const float* x = (const float*)d_in[0];
    PackPtrs pp;
    for (int t = 0; t < 4; t++) {
        int base = 1 + t*5;
        pp.wi[t] = (const float*)d_in[base+0];
        pp.bi[t] = (const float*)d_in[base+1];
        pp.al[t] = (const float*)d_in[base+2];
        pp.wb[t] = (const float*)d_in[base+3];
        pp.bb[t] = (const float*)d_in[base+4];
    }
    const float* wl = (const float*)d_in[21];
    float* out = (float*)d_out;

    cudaFuncSetAttribute(dct_spatial_kernel, cudaFuncAttributeMaxDynamicSharedMemorySize, DCT_SMEM);
    cudaFuncSetAttribute(conv_fused_kernel, cudaFuncAttributeMaxDynamicSharedMemorySize, CONV_SMEM);

    init_mats_kernel<<<64, 256>>>();
    pack_kernel<<<64, 256>>>(pp);

    dct_spatial_kernel<<<486, 256, DCT_SMEM>>>(x, out, 0);   // x -> g_b1
    dct_ang_kernel<<<192, 256>>>(0);                          // g_b1 -> g_b2

    conv_fused_kernel<<<CGRID, 256, CONV_SMEM>>>(wl);         // g_b2 -> ... -> g_b1

    dct_ang_kernel<<<192, 256>>>(1);                          // g_b1 -> g_b2
    dct_spatial_kernel<<<486, 256, DCT_SMEM>>>(x, out, 1);    // g_b2 -> out (+x)
}

// round 13
// speedup vs baseline: 1.2977x; 1.2977x over previous
#include <cuda_runtime.h>
#include <math.h>

#ifndef M_PI
#define M_PI 3.14159265358979323846
#endif

#define ANGN 9
#define NUV 81
#define CH 3
#define HH 128
#define NF 16
#define NBLK 2
#define HW (HH*HH)            // 16384
#define S_UVHW (NUV*HW)       // 1327104

typedef unsigned long long ull;

__device__ __forceinline__ ull pack2(float lo, float hi) {
    ull r; asm("mov.b64 %0,{%1,%2};" : "=l"(r) : "f"(lo), "f"(hi)); return r;
}
__device__ __forceinline__ void unpack2(ull v, float& lo, float& hi) {
    asm("mov.b64 {%0,%1},%2;" : "=f"(lo), "=f"(hi) : "l"(v));
}
__device__ __forceinline__ void fma2(ull& d, ull a, ull b) {
    asm("fma.rn.f32x2 %0,%1,%2,%0;" : "+l"(d) : "l"(a), "l"(b));
}

// ---------------- device global scratch ----------------
__device__ float g_Ds[HH*HH];
__device__ float g_DsT[HH*HH];
__device__ float g_Da[81];
__device__ float g_DaT[81];

__device__ float g_b1[CH*S_UVHW];
__device__ float g_b2[CH*S_UVHW];
__device__ float g_y0[NF*S_UVHW];
__device__ float g_y1[NF*S_UVHW];
__device__ float g_p0[NF*S_UVHW];   // prelu(y0, a0)
__device__ float g_p1[NF*S_UVHW];   // prelu(y1, a1)

// transposed weights: [set][(ic*27+t)*NF + o]
__device__ float g_wti[4*CH*27*NF];        // init conv (4 branches)
__device__ float g_wtb[4*NBLK*NF*27*NF];   // resblocks (8 sets)
__device__ float g_bi[4*NF];
__device__ float g_bb[4*NBLK*NF];
__device__ float g_al[4*NBLK];             // prelu alphas

// ---------------- fused init: DCT matrices (cosf, exact int reduction) + pack
struct PackPtrs {
    const float* wi[4];
    const float* bi[4];
    const float* al[4];
    const float* wb[4];
    const float* bb[4];
};

__global__ void setup_kernel(PackPtrs pp) {
    int tid = blockIdx.x*blockDim.x + threadIdx.x;
    int stride = gridDim.x*blockDim.x;
    const float sc_s = sqrtf(2.0f/HH);
    const float st_s = (float)(M_PI/256.0);   // pi/(2*128)
    for (int idx = tid; idx < HH*HH; idx += stride) {
        int k = idx / HH, i = idx % HH;
        int m = ((2*i+1)*k) & 511;             // mod 4n, n=128
        float f = cosf((float)m * st_s) * sc_s;
        if (k==0) f *= 0.70710678f;
        g_Ds[k*HH+i] = f;
        g_DsT[i*HH+k] = f;
    }
    const float sc_a = sqrtf(2.0f/9.0f);
    const float st_a = (float)(M_PI/18.0);
    for (int idx = tid; idx < 81; idx += stride) {
        int k = idx/9, i = idx%9;
        int m = ((2*i+1)*k) % 36;
        float f = cosf((float)m * st_a) * sc_a;
        if (k==0) f *= 0.70710678f;
        g_Da[k*9+i] = f;
        g_DaT[i*9+k] = f;
    }
    // weight transpose-pack
    for (int i = tid; i < 4*CH*27*NF; i += stride) {
        int widx = i / (CH*27*NF);
        int r = i - widx*(CH*27*NF);
        int ict = r >> 4, o = r & 15;
        g_wti[i] = pp.wi[widx][o*(CH*27) + ict];
    }
    for (int i = tid; i < 4*NBLK*NF*27*NF; i += stride) {
        int sel = i / (NF*27*NF);
        int r = i - sel*(NF*27*NF);
        int ict = r >> 4, o = r & 15;
        int branch = sel >> 1, k = sel & 1;
        g_wtb[i] = pp.wb[branch][k*(NF*NF*27) + o*(NF*27) + ict];
    }
    for (int i = tid; i < 4*NF; i += stride)       g_bi[i] = pp.bi[i/NF][i%NF];
    for (int i = tid; i < 4*NBLK; i += stride)     g_al[i] = pp.al[i/NBLK][i%NBLK];
    for (int i = tid; i < 4*NBLK*NF; i += stride)  g_bb[i] = pp.bb[i/(NBLK*NF)][i%(NBLK*NF)];
}

// ---------------- spatial DCT: Y = M X M^T per 128x128 image ----------------
// 486 blocks: (uv,c) x half. Each block computes 64 output rows.
#define DPAD 129
#define DCT_SMEM ((2*HH + 64)*DPAD*4)

__global__ void dct_spatial_kernel(const float* __restrict__ x, float* __restrict__ dout, int mode) {
    extern __shared__ float sm[];
    float* Ms = sm;
    float* Xs = sm + HH*DPAD;
    float* Ts = sm + 2*HH*DPAD;     // 64 rows
    int bid = blockIdx.x;           // 0..485
    int half = bid & 1;
    int uvc = bid >> 1;
    int uv = uvc / CH, c = uvc % CH;
    int r0 = half*64;
    int tid = threadIdx.x;

    const float* Msrc = mode ? g_DsT : g_Ds;
    const float* src  = mode ? (g_b2 + (c*NUV+uv)*HW) : (x + (uv*CH+c)*HW);

    for (int l = tid; l < HH*HH; l += 256) {
        int r = l >> 7, cc = l & 127;
        Ms[r*DPAD + cc] = Msrc[l];
        Xs[r*DPAD + cc] = src[l];
    }
    __syncthreads();

    int tx = tid & 15, ty = tid >> 4;
    ull acc[4][4];
    #pragma unroll
    for (int i=0;i<4;i++)
        #pragma unroll
        for (int jp=0;jp<4;jp++) acc[i][jp] = 0ull;

    for (int kk = 0; kk < HH; kk++) {
        ull ad[4], bp[4];
        #pragma unroll
        for (int i=0;i<4;i++) {
            float a = Ms[(r0+ty+16*i)*DPAD + kk];
            ad[i] = pack2(a, a);
        }
        #pragma unroll
        for (int jp=0;jp<4;jp++)
            bp[jp] = pack2(Xs[kk*DPAD + tx + 32*jp], Xs[kk*DPAD + tx + 32*jp + 16]);
        #pragma unroll
        for (int i=0;i<4;i++)
            #pragma unroll
            for (int jp=0;jp<4;jp++) fma2(acc[i][jp], ad[i], bp[jp]);
    }
    #pragma unroll
    for (int i=0;i<4;i++)
        #pragma unroll
        for (int jp=0;jp<4;jp++) {
            float lo, hi; unpack2(acc[i][jp], lo, hi);
            Ts[(ty+16*i)*DPAD + tx + 32*jp]      = lo;
            Ts[(ty+16*i)*DPAD + tx + 32*jp + 16] = hi;
        }
    __syncthreads();

    #pragma unroll
    for (int i=0;i<4;i++)
        #pragma unroll
        for (int jp=0;jp<4;jp++) acc[i][jp] = 0ull;

    for (int kk = 0; kk < HH; kk++) {
        ull ad[4], bp[4];
        #pragma unroll
        for (int i=0;i<4;i++) {
            float a = Ts[(ty+16*i)*DPAD + kk];
            ad[i] = pack2(a, a);
        }
        #pragma unroll
        for (int jp=0;jp<4;jp++)
            bp[jp] = pack2(Ms[(tx+32*jp)*DPAD + kk], Ms[(tx+32*jp+16)*DPAD + kk]);
        #pragma unroll
        for (int i=0;i<4;i++)
            #pragma unroll
            for (int jp=0;jp<4;jp++) fma2(acc[i][jp], ad[i], bp[jp]);
    }

    if (mode == 0) {
        float* dst = g_b1 + (c*NUV+uv)*HW;
        #pragma unroll
        for (int i=0;i<4;i++)
            #pragma unroll
            for (int jp=0;jp<4;jp++) {
                float lo, hi; unpack2(acc[i][jp], lo, hi);
                dst[(r0+ty+16*i)*HH + tx+32*jp]      = lo;
                dst[(r0+ty+16*i)*HH + tx+32*jp + 16] = hi;
            }
    } else {
        const float* xa = x + (uv*CH+c)*HW;
        float* dst = dout + (uv*CH+c)*HW;
        #pragma unroll
        for (int i=0;i<4;i++)
            #pragma unroll
            for (int jp=0;jp<4;jp++) {
                float lo, hi; unpack2(acc[i][jp], lo, hi);
                int o0 = (r0+ty+16*i)*HH + tx+32*jp;
                int o1 = o0 + 16;
                dst[o0] = lo + xa[o0];
                dst[o1] = hi + xa[o1];
            }
    }
}

// ---------------- angular DCT: per (c,h,w), O = M A M^T over 9x9 ----------------
__global__ void dct_ang_kernel(int mode) {
    __shared__ float M[81];
    int tid = threadIdx.x;
    if (tid < 81) M[tid] = mode ? g_DaT[tid] : g_Da[tid];
    __syncthreads();
    int g = blockIdx.x*blockDim.x + tid;     // 0..49151
    if (g >= CH*HW) return;
    int c = g / HW, p = g % HW;

    const float* in = g_b1 + c*S_UVHW + p;
    float T[81];
    #pragma unroll
    for (int i=0;i<81;i++) T[i] = 0.f;

    #pragma unroll
    for (int u=0;u<9;u++) {
        #pragma unroll
        for (int v=0;v<9;v++) {
            float xv = in[(u*9+v)*HW];
            #pragma unroll
            for (int U=0;U<9;U++) T[U*9+v] += M[U*9+u]*xv;
        }
    }
    float* outp = g_b2 + c*S_UVHW + p;
    #pragma unroll
    for (int U=0;U<9;U++) {
        #pragma unroll
        for (int V=0;V<9;V++) {
            float o = 0.f;
            #pragma unroll
            for (int v=0;v<9;v++) o += T[U*9+v]*M[V*9+v];
            outp[(U*9+V)*HW] = o;
        }
    }
}

// ---------------- 3x3x3 conv over (uv-diagonal, h, w), f32x2 oc-paired -------
// tile: 16 rows x 64 cols, 256 threads, each thread 4 px, 16 oc as 8 oc-pairs.
// Input pre-activated. cp.async double-buffered fills, zfill boundaries.
// MIX variant fuses the final 1x1 conv (y0 + y2 -> 3ch) into the epilogue.
#define TPL (18*66)          // 1188
#define TPL3 (3*TPL)         // 3564
#define CONVB_SMEM ((NF*NF*27 + NF + 48 + 2*TPL3)*4)
#define CONVI_SMEM ((CH*NF*27 + NF + 48 + 2*TPL3)*4)

template<int CIN, bool RES, bool WRITE_P, bool MIX>
__device__ __forceinline__ void conv3d_body(
    const float* __restrict__ in, const float* __restrict__ res,
    float* __restrict__ out, float* __restrict__ pout, float palpha,
    const float* __restrict__ Wt, const float* __restrict__ Bsel,
    const float* __restrict__ wl, const float* __restrict__ mix_extra,
    float* __restrict__ mix_out)
{
    extern __shared__ float sm[];
    float* sw = sm;                         // CIN*27*NF floats, [ict][o]
    float* sb = sw + CIN*27*NF;
    float* sl = sb + NF;                    // 48 mix weights
    float* st = sl + 48;                    // even word offset -> 8B aligned
    const ull* swp = (const ull*)sw;

    const int tid = threadIdx.x;
    const int tx = tid & 15, ty = tid >> 4;
    const int uv = blockIdx.z;
    const int u = uv/9, v = uv - 9*u;
    const int h0 = blockIdx.y*16, w0 = blockIdx.x*64;
    const int nb0 = (u > 0 && v < 8) ? uv-8 : -1;   // (u-1,v+1)
    const int nb2 = (u < 8 && v > 0) ? uv+8 : -1;   // (u+1,v-1)

    for (int l = tid; l < CIN*27*NF; l += 256) sw[l] = Wt[l];
    if (tid < NF) sb[tid] = Bsel[tid];
    if (MIX && tid < CH*NF) sl[tid] = wl[tid];

    int offs[14]; unsigned vmask = 0;
    #pragma unroll
    for (int j = 0; j < 14; j++) {
        int l = tid + j*256;
        offs[j] = 0;
        if (l < TPL3) {
            int d = l / TPL;
            int rem = l - d*TPL;
            int r = rem / 66;
            int cc = rem - r*66;
            int gh = h0 - 1 + r, gw = w0 - 1 + cc;
            int uvd = (d==0) ? nb0 : ((d==1) ? uv : nb2);
            if (uvd >= 0 && (unsigned)gh < (unsigned)HH && (unsigned)gw < (unsigned)HH) {
                vmask |= 1u << j;
                offs[j] = (uvd << 14) + (gh << 7) + gw;
            }
        }
    }

    auto fill = [&](const float* icin, float* nbuf) {
        unsigned sbase = (unsigned)__cvta_generic_to_shared(nbuf);
        #pragma unroll
        for (int j = 0; j < 14; j++) {
            int l = tid + j*256;
            if (l < TPL3) {
                unsigned sa = sbase + (unsigned)l*4u;
                const float* ga = icin + offs[j];
                int sz = ((vmask >> j) & 1u) ? 4 : 0;
                asm volatile("cp.async.ca.shared.global [%0], [%1], 4, %2;"
                             :: "r"(sa), "l"(ga), "r"(sz));
            }
        }
        asm volatile("cp.async.commit_group;");
    };

    fill(in, st);
    asm volatile("cp.async.wait_group 0;");
    __syncthreads();

    ull acc[8][4];
    #pragma unroll
    for (int op=0;op<8;op++)
        #pragma unroll
        for (int p=0;p<4;p++) acc[op][p] = 0ull;

    #pragma unroll 1
    for (int ic = 0; ic < CIN; ic++) {
        if (ic + 1 < CIN) fill(in + (ic+1)*(NUV*HW), st + ((ic+1) & 1)*TPL3);

        const float* base = st + (ic & 1)*TPL3;
        #pragma unroll 1
        for (int d = 0; d < 3; d++) {
            if (d == 0 && nb0 < 0) continue;
            if (d == 2 && nb2 < 0) continue;
            #pragma unroll
            for (int dh = 0; dh < 3; dh++) {
                const ull* row = (const ull*)(base + d*TPL + (ty+dh)*66 + tx*4);
                ull p01 = row[0], p23 = row[1], p45 = row[2];
                float i0,i1,i2,i3,i4,i5;
                unpack2(p01, i0, i1); unpack2(p23, i2, i3); unpack2(p45, i4, i5);
                ull dd0 = pack2(i0,i0), dd1 = pack2(i1,i1), dd2 = pack2(i2,i2);
                ull dd3 = pack2(i3,i3), dd4 = pack2(i4,i4), dd5 = pack2(i5,i5);
                ull dv[6] = {dd0, dd1, dd2, dd3, dd4, dd5};
                const ulonglong2* wt2 = (const ulonglong2*)(swp + (ic*27 + d*9 + dh*3)*(NF/2));
                #pragma unroll
                for (int dw = 0; dw < 3; dw++) {
                    #pragma unroll
                    for (int q = 0; q < 4; q++) {
                        ulonglong2 wp = wt2[dw*4 + q];
                        int op = 2*q;
                        fma2(acc[op][0], dv[dw+0], wp.x);
                        fma2(acc[op][1], dv[dw+1], wp.x);
                        fma2(acc[op][2], dv[dw+2], wp.x);
                        fma2(acc[op][3], dv[dw+3], wp.x);
                        fma2(acc[op+1][0], dv[dw+0], wp.y);
                        fma2(acc[op+1][1], dv[dw+1], wp.y);
                        fma2(acc[op+1][2], dv[dw+2], wp.y);
                        fma2(acc[op+1][3], dv[dw+3], wp.y);
                    }
                }
            }
        }
        if (ic + 1 < CIN) {
            asm volatile("cp.async.wait_group 0;");
            __syncthreads();
        }
    }

    const int gh = h0 + ty;
    const int pbase = (gh << 7) + w0 + tx*4;
    float4 macc[3];
    if (MIX) { macc[0] = make_float4(0,0,0,0); macc[1] = macc[0]; macc[2] = macc[0]; }

    #pragma unroll
    for (int op = 0; op < 8; op++) {
        float e0[4], e1[4];
        #pragma unroll
        for (int p = 0; p < 4; p++) unpack2(acc[op][p], e0[p], e1[p]);
        #pragma unroll
        for (int half = 0; half < 2; half++) {
            int o = 2*op + half;
            const float* ev = half ? e1 : e0;
            float bias = sb[o];
            int obase = ((o*NUV+uv) << 14) + pbase;
            float4 r4;
            r4.x = ev[0] + bias; r4.y = ev[1] + bias;
            r4.z = ev[2] + bias; r4.w = ev[3] + bias;
            if (RES) {
                float4 rr = *(const float4*)&res[obase];
                r4.x += rr.x; r4.y += rr.y; r4.z += rr.z; r4.w += rr.w;
            }
            if (MIX) {
                float4 y0v = *(const float4*)&mix_extra[obase];
                float tx0 = r4.x + y0v.x, tx1 = r4.y + y0v.y;
                float tx2 = r4.z + y0v.z, tx3 = r4.w + y0v.w;
                #pragma unroll
                for (int cc = 0; cc < 3; cc++) {
                    float wv = sl[cc*NF + o];
                    macc[cc].x += wv*tx0; macc[cc].y += wv*tx1;
                    macc[cc].z += wv*tx2; macc[cc].w += wv*tx3;
                }
            } else {
                *(float4*)&out[obase] = r4;
                if (WRITE_P) {
                    float4 p4;
                    p4.x = (r4.x >= 0.f) ? r4.x : palpha*r4.x;
                    p4.y = (r4.y >= 0.f) ? r4.y : palpha*r4.y;
                    p4.z = (r4.z >= 0.f) ? r4.z : palpha*r4.z;
                    p4.w = (r4.w >= 0.f) ? r4.w : palpha*r4.w;
                    *(float4*)&pout[obase] = p4;
                }
            }
        }
    }
    if (MIX) {
        #pragma unroll
        for (int cc = 0; cc < 3; cc++)
            *(float4*)&mix_out[((cc*NUV+uv) << 14) + pbase] = macc[cc];
    }
}

__device__ __forceinline__ int branch_idx(int uv) {
    int u = uv/9, s = u + (uv - 9*u);
    return (s==0) ? 0 : (s<=2 ? 1 : (s<=8 ? 2 : 3));
}

__global__ void __launch_bounds__(256,2) conv_init_kernel() {
    int widx = branch_idx(blockIdx.z);
    float pa = g_al[widx*NBLK + 0];
    conv3d_body<CH,false,true,false>(g_b2, nullptr, g_y0, g_p0, pa,
        g_wti + widx*(CH*27*NF), g_bi + widx*NF, nullptr, nullptr, nullptr);
}

__global__ void __launch_bounds__(256,2) conv_block0_kernel() {
    int widx = branch_idx(blockIdx.z);
    float pa = g_al[widx*NBLK + 1];
    int sel = widx*NBLK + 0;
    conv3d_body<NF,true,true,false>(g_p0, g_y0, g_y1, g_p1, pa,
        g_wtb + sel*(NF*27*NF), g_bb + sel*NF, nullptr, nullptr, nullptr);
}

__global__ void __launch_bounds__(256,2) conv_block1_kernel(const float* __restrict__ wl) {
    int widx = branch_idx(blockIdx.z);
    int sel = widx*NBLK + 1;
    conv3d_body<NF,true,false,true>(g_p1, g_y1, nullptr, nullptr, 0.f,
        g_wtb + sel*(NF*27*NF), g_bb + sel*NF, wl, g_y0, g_b1);
}

// ---------------- launch ----------------
extern "C" void kernel_launch(void* const* d_in, const int* in_sizes, int n_in,
                              void* d_out, int out_size) {
    const float* x = (const float*)d_in[0];
    PackPtrs pp;
    for (int t = 0; t < 4; t++) {
        int base = 1 + t*5;
        pp.wi[t] = (const float*)d_in[base+0];
        pp.bi[t] = (const float*)d_in[base+1];
        pp.al[t] = (const float*)d_in[base+2];
        pp.wb[t] = (const float*)d_in[base+3];
        pp.bb[t] = (const float*)d_in[base+4];
    }
    const float* wl = (const float*)d_in[21];
    float* out = (float*)d_out;

    cudaFuncSetAttribute(dct_spatial_kernel, cudaFuncAttributeMaxDynamicSharedMemorySize, DCT_SMEM);
    cudaFuncSetAttribute(conv_init_kernel, cudaFuncAttributeMaxDynamicSharedMemorySize, CONVI_SMEM);
    cudaFuncSetAttribute(conv_block0_kernel, cudaFuncAttributeMaxDynamicSharedMemorySize, CONVB_SMEM);
    cudaFuncSetAttribute(conv_block1_kernel, cudaFuncAttributeMaxDynamicSharedMemorySize, CONVB_SMEM);

    setup_kernel<<<64, 256>>>(pp);

    dct_spatial_kernel<<<486, 256, DCT_SMEM>>>(x, out, 0);   // x -> g_b1
    dct_ang_kernel<<<192, 256>>>(0);                          // g_b1 -> g_b2

    dim3 cg(2, 8, NUV);
    conv_init_kernel<<<cg, 256, CONVI_SMEM>>>();              // g_b2 -> y0, p0
    conv_block0_kernel<<<cg, 256, CONVB_SMEM>>>();            // p0,y0 -> y1, p1
    conv_block1_kernel<<<cg, 256, CONVB_SMEM>>>(wl);          // p1,y1,y0 -> mix -> g_b1

    dct_ang_kernel<<<192, 256>>>(1);                          // g_b1 -> g_b2
    dct_spatial_kernel<<<486, 256, DCT_SMEM>>>(x, out, 1);    // g_b2 -> out (+x)
}